// round 13
// baseline (speedup 1.0000x reference)
#include <cuda_runtime.h>
#include <math.h>

#define M_PTS    2048
#define N_VOX    65536
#define TPB      256
#define GRID     (N_VOX / TPB)           // 256 blocks, 1 voxel per thread
#define PPT      (M_PTS / TPB)           // 8 points per thread
#define NPGRID   10                      // point grid: 10^3 cells, pitch 0.5 (q-space), [-2.5,2.5)
#define NPCELL   1000
#define NPPAD    1024
#define NVB      9                       // voxel base-cell grid 9^3 = 729
#define NVPAD    768                     // padded to 3*TPB

__device__ float4 g_part[GRID];          // per-block partials {pred_sum, s1, s2, mask_sum}
__device__ unsigned g_done = 0;          // zero-init; self-resetting each run

struct Smem {
    float4 pts[M_PTS];        // block-private cell-sorted points (32 KB)
    float4 vsort[TPB];        // voxels sorted by base cell {ux,uy,uz,bits(cellid)}
    float2 vfm[TPB];          // {free+occ, mask} per sorted voxel
    int    cnt[NPPAD];        // point histogram
    int    cur[NPCELL];       // point scatter cursors
    int    cstart[NPCELL + 1];
    int    vhist[NVPAD];      // voxel histogram
    int    vcur[NVPAD];       // voxel scatter cursors (exclusive starts)
    float  cof[16], iA[16], Em[16], Ms[16];
    float  red[4][TPB / 32];
    int    wa[TPB / 32];
    unsigned amLast;
};

__global__ void __launch_bounds__(TPB) icc_kernel(
    const float* __restrict__ quat,    const float* __restrict__ tran,
    const float* __restrict__ model,   const float* __restrict__ view,
    const float* __restrict__ centers, const float* __restrict__ freev,
    const float* __restrict__ occo,    const float* __restrict__ masks,
    float* __restrict__ out) {
    extern __shared__ char raw[];
    Smem* sm = (Smem*)raw;
    const int t = threadIdx.x;
    const int lane = t & 31, w = t >> 5;

    // ---- voxel-side loads early (independent of everything) ----
    const int v = blockIdx.x * TPB + t;
    const float cx = centers[3 * v + 0];
    const float cy = centers[3 * v + 1];
    const float cz = centers[3 * v + 2];
    const float fo = freev[v] + occo[v];
    const float mk = masks[v];

    for (int i = t; i < NPPAD; i += TPB) sm->cnt[i] = 0;

    // ---- parallel mat_world = inv(view) @ quat_matrix: 16 lanes, adjugate ----
    if (t < 16) {
        const int r = t >> 2, c = t & 3;
        float V[16];
#pragma unroll
        for (int k = 0; k < 16; k++) V[k] = view[k];
        // cofactor(r,c): signed det of 3x3 minor
        int rr[3], cc[3];
        {
            int i0 = 0, i1 = 0;
#pragma unroll
            for (int k = 0; k < 4; k++) { if (k != r) rr[i0++] = k; if (k != c) cc[i1++] = k; }
        }
        float a00 = V[rr[0] * 4 + cc[0]], a01 = V[rr[0] * 4 + cc[1]], a02 = V[rr[0] * 4 + cc[2]];
        float a10 = V[rr[1] * 4 + cc[0]], a11 = V[rr[1] * 4 + cc[1]], a12 = V[rr[1] * 4 + cc[2]];
        float a20 = V[rr[2] * 4 + cc[0]], a21 = V[rr[2] * 4 + cc[1]], a22 = V[rr[2] * 4 + cc[2]];
        float det3 = a00 * (a11 * a22 - a12 * a21)
                   - a01 * (a10 * a22 - a12 * a20)
                   + a02 * (a10 * a21 - a11 * a20);
        sm->cof[t] = (((r + c) & 1) ? -det3 : det3);   // cof[r*4+c]
        __syncwarp(0x0000ffffu);
        float det = V[0] * sm->cof[0] + V[1] * sm->cof[1] + V[2] * sm->cof[2] + V[3] * sm->cof[3];
        float rdet = 1.0f / det;
        sm->iA[t] = sm->cof[c * 4 + r] * rdet;         // inv[r][c] = cof[c][r]/det

        // E[r][c] from quaternion
        float q0 = quat[0], q1 = quat[1], q2 = quat[2], q3 = quat[3];
        float s = q0 * q0 + q1 * q1 + q2 * q2 + q3 * q3;
        float f = sqrtf(2.0f / s);
        q0 *= f; q1 *= f; q2 *= f; q3 *= f;
        float e;
        switch (t) {
            case 0:  e = 1.0f - q2 * q2 - q3 * q3; break;
            case 1:  e = q1 * q2 - q3 * q0;        break;
            case 2:  e = q1 * q3 + q2 * q0;        break;
            case 3:  e = tran[0];                  break;
            case 4:  e = q1 * q2 + q3 * q0;        break;
            case 5:  e = 1.0f - q1 * q1 - q3 * q3; break;
            case 6:  e = q2 * q3 - q1 * q0;        break;
            case 7:  e = tran[1];                  break;
            case 8:  e = q1 * q3 - q2 * q0;        break;
            case 9:  e = q2 * q3 + q1 * q0;        break;
            case 10: e = 1.0f - q1 * q1 - q2 * q2; break;
            case 11: e = tran[2];                  break;
            case 15: e = 1.0f;                     break;
            default: e = 0.0f;                     break;
        }
        sm->Em[t] = e;
        __syncwarp(0x0000ffffu);
        sm->Ms[t] = sm->iA[r * 4 + 0] * sm->Em[0 * 4 + c]
                  + sm->iA[r * 4 + 1] * sm->Em[1 * 4 + c]
                  + sm->iA[r * 4 + 2] * sm->Em[2 * 4 + c]
                  + sm->iA[r * 4 + 3] * sm->Em[3 * 4 + c];
    }
    __syncthreads();

    // ---- transform 8 points/thread into registers; histogram ----
    float rx[PPT], ry[PPT], rz[PPT];
    int   rc[PPT];
#pragma unroll
    for (int k = 0; k < PPT; k++) {
        int i = k * TPB + t;                       // coalesced
        float mx = model[3 * i + 0], my = model[3 * i + 1], mz = model[3 * i + 2];
        const float* Ms = sm->Ms;
        float hx = Ms[0]  * mx + Ms[1]  * my + Ms[2]  * mz + Ms[3];
        float hy = Ms[4]  * mx + Ms[5]  * my + Ms[6]  * mz + Ms[7];
        float hz = Ms[8]  * mx + Ms[9]  * my + Ms[10] * mz + Ms[11];
        float hw = Ms[12] * mx + Ms[13] * my + Ms[14] * mz + Ms[15];
        float inv = 2.0f / hw;                      // pred / RES
        float x = hx * inv, y = hy * inv, z = hz * inv;
        rx[k] = x; ry[k] = y; rz[k] = z;
        int ix = (int)floorf(2.0f * x + 5.0f);
        int iy = (int)floorf(2.0f * y + 5.0f);
        int iz = (int)floorf(2.0f * z + 5.0f);
        int cell = -1;
        // points outside [-2.5,2.5)^3 are > 0.25 (L2) from every center in
        // [-2,2)^3 (q-space) -> the RES/2 clamp makes them irrelevant: discard.
        if (ix >= 0 && ix < NPGRID && iy >= 0 && iy < NPGRID && iz >= 0 && iz < NPGRID) {
            cell = (ix * NPGRID + iy) * NPGRID + iz;
            atomicAdd(&sm->cnt[cell], 1);
        }
        rc[k] = cell;
    }
    __syncthreads();

    // ---- exclusive scan over 1024 point cells (4/thread) ----
    {
        int bidx = t * 4;
        int s4[4]; int tot = 0;
#pragma unroll
        for (int j = 0; j < 4; j++) { s4[j] = tot; tot += sm->cnt[bidx + j]; }
        int incl = tot;
#pragma unroll
        for (int off = 1; off < 32; off <<= 1) {
            int u = __shfl_up_sync(0xffffffffu, incl, off);
            if (lane >= off) incl += u;
        }
        if (lane == 31) sm->wa[w] = incl;
        __syncthreads();
        if (t < 8) {
            int u = sm->wa[t];
#pragma unroll
            for (int off = 1; off < 8; off <<= 1) {
                int x2 = __shfl_up_sync(0x000000ffu, u, off);
                if (t >= off) u += x2;
            }
            sm->wa[t] = u;
        }
        __syncthreads();
        int excl = ((w > 0) ? sm->wa[w - 1] : 0) + incl - tot;
#pragma unroll
        for (int j = 0; j < 4; j++) {
            int idx = bidx + j;
            if (idx < NPCELL) { int sv = excl + s4[j]; sm->cstart[idx] = sv; sm->cur[idx] = sv; }
        }
        if (bidx <= NPCELL && NPCELL < bidx + 4) sm->cstart[NPCELL] = excl + s4[NPCELL - bidx];
    }
    __syncthreads();

    // ---- scatter points into block-private sorted table ----
#pragma unroll
    for (int k = 0; k < PPT; k++) {
        int cell = rc[k];
        if (cell >= 0) {
            int pos = atomicAdd(&sm->cur[cell], 1);
            sm->pts[pos] = make_float4(rx[k], ry[k], rz[k], 0.0f);
        }
    }

    // ---- sort this block's 256 voxels by base cell (coherent warps in query) ----
    const int ix0 = (int)floorf(4.0f * cx + 4.5f);   // in [0,8]
    const int iy0 = (int)floorf(4.0f * cy + 4.5f);
    const int iz0 = (int)floorf(4.0f * cz + 4.5f);
    const int vcid = (ix0 * NVB + iy0) * NVB + iz0;

    for (int i = t; i < NVPAD; i += TPB) sm->vhist[i] = 0;
    __syncthreads();
    atomicAdd(&sm->vhist[vcid], 1);
    __syncthreads();
    {
        // exclusive scan over 768 voxel bins (3/thread)
        int b3 = t * 3;
        int h0 = sm->vhist[b3], h1 = sm->vhist[b3 + 1], h2 = sm->vhist[b3 + 2];
        int tot = h0 + h1 + h2;
        int incl = tot;
#pragma unroll
        for (int off = 1; off < 32; off <<= 1) {
            int u = __shfl_up_sync(0xffffffffu, incl, off);
            if (lane >= off) incl += u;
        }
        if (lane == 31) sm->wa[w] = incl;
        __syncthreads();
        if (t < 8) {
            int u = sm->wa[t];
#pragma unroll
            for (int off = 1; off < 8; off <<= 1) {
                int x2 = __shfl_up_sync(0x000000ffu, u, off);
                if (t >= off) u += x2;
            }
            sm->wa[t] = u;
        }
        __syncthreads();
        int excl = ((w > 0) ? sm->wa[w - 1] : 0) + incl - tot;
        sm->vcur[b3]     = excl;
        sm->vcur[b3 + 1] = excl + h0;
        sm->vcur[b3 + 2] = excl + h0 + h1;
    }
    __syncthreads();
    {
        int pos = atomicAdd(&sm->vcur[vcid], 1);
        sm->vsort[pos] = make_float4(2.0f * cx, 2.0f * cy, 2.0f * cz, __int_as_float(vcid));
        sm->vfm[pos]   = make_float2(fo, mk);
    }
    __syncthreads();

    // ---- query: sorted voxel t against its 2x2x2 cell neighborhood ----
    float4 vp = sm->vsort[t];
    float2 fm = sm->vfm[t];
    const float ux = vp.x, uy = vp.y, uz = vp.z;
    const int cid = __float_as_int(vp.w);
    const int jx0 = cid / (NVB * NVB);
    const int jy0 = (cid / NVB) % NVB;
    const int jz0 = cid % NVB;

    float m0 = 1e30f, m1 = 1e30f, m2 = 1e30f, m3 = 1e30f;
#pragma unroll
    for (int a = 0; a < 2; a++) {
#pragma unroll
        for (int b = 0; b < 2; b++) {
            int cb = ((jx0 + a) * NPGRID + (jy0 + b)) * NPGRID + jz0;
            int s = sm->cstart[cb];
            int e = sm->cstart[cb + 2];              // z-cells jz0, jz0+1 contiguous
            int k = s;
            for (; k + 4 <= e; k += 4) {             // 4 independent chains
                float4 p0 = sm->pts[k];
                float4 p1 = sm->pts[k + 1];
                float4 p2 = sm->pts[k + 2];
                float4 p3 = sm->pts[k + 3];
                float dx0 = ux - p0.x, dy0 = uy - p0.y, dz0 = uz - p0.z;
                float dx1 = ux - p1.x, dy1 = uy - p1.y, dz1 = uz - p1.z;
                float dx2 = ux - p2.x, dy2 = uy - p2.y, dz2 = uz - p2.z;
                float dx3 = ux - p3.x, dy3 = uy - p3.y, dz3 = uz - p3.z;
                m0 = fminf(m0, fmaf(dx0, dx0, fmaf(dy0, dy0, dz0 * dz0)));
                m1 = fminf(m1, fmaf(dx1, dx1, fmaf(dy1, dy1, dz1 * dz1)));
                m2 = fminf(m2, fmaf(dx2, dx2, fmaf(dy2, dy2, dz2 * dz2)));
                m3 = fminf(m3, fmaf(dx3, dx3, fmaf(dy3, dy3, dz3 * dz3)));
            }
            for (; k < e; k++) {
                float4 p = sm->pts[k];
                float dx = ux - p.x, dy = uy - p.y, dz = uz - p.z;
                m0 = fminf(m0, fmaf(dx, dx, fmaf(dy, dy, dz * dz)));
            }
        }
    }
    float m = fminf(fminf(m0, m1), fminf(m2, m3));

    float d = sqrtf(fmaxf(m, 0.0f));
    d = fminf(d, 0.25f);
    float o = fmaxf(1.0f - 4.0f * d, 0.0f);

    float aps = o, as1 = fm.x * o, as2 = fm.y * o, ams = fm.y;

    const unsigned full = 0xffffffffu;
#pragma unroll
    for (int off = 16; off > 0; off >>= 1) {
        aps += __shfl_down_sync(full, aps, off);
        as1 += __shfl_down_sync(full, as1, off);
        as2 += __shfl_down_sync(full, as2, off);
        ams += __shfl_down_sync(full, ams, off);
    }
    if (lane == 0) { sm->red[0][w] = aps; sm->red[1][w] = as1; sm->red[2][w] = as2; sm->red[3][w] = ams; }
    __syncthreads();
    if (t == 0) {
        float tps = 0.f, ts1 = 0.f, ts2 = 0.f, tms = 0.f;
#pragma unroll
        for (int i = 0; i < TPB / 32; i++) {
            tps += sm->red[0][i]; ts1 += sm->red[1][i];
            ts2 += sm->red[2][i]; tms += sm->red[3][i];
        }
        g_part[blockIdx.x] = make_float4(tps, ts1, ts2, tms);
        __threadfence();
        unsigned r = atomicAdd(&g_done, 1u);
        sm->amLast = (r == GRID - 1) ? 1u : 0u;
    }
    __syncthreads();

    // ---- last-finished block folds all partials into the scalar output ----
    if (sm->amLast) {
        float4 p = __ldcg(&g_part[t]);               // t in [0, 256) == GRID
#pragma unroll
        for (int off = 16; off > 0; off >>= 1) {
            p.x += __shfl_down_sync(full, p.x, off);
            p.y += __shfl_down_sync(full, p.y, off);
            p.z += __shfl_down_sync(full, p.z, off);
            p.w += __shfl_down_sync(full, p.w, off);
        }
        if (lane == 0) { sm->red[0][w] = p.x; sm->red[1][w] = p.y; sm->red[2][w] = p.z; sm->red[3][w] = p.w; }
        __syncthreads();
        if (t == 0) {
            double ps = 0.0, s1 = 0.0, s2 = 0.0, ms = 0.0;
#pragma unroll
            for (int i = 0; i < TPB / 32; i++) {
                ps += (double)sm->red[0][i]; s1 += (double)sm->red[1][i];
                s2 += (double)sm->red[2][i]; ms += (double)sm->red[3][i];
            }
            double t1 = (ps > 0.0) ? s1 / ps : 0.0;
            double t2 = (ms > 0.0) ? s2 / ms : 0.0;
            out[0] = (float)(t1 - t2);
            g_done = 0;                               // reset for next graph replay
        }
    }
}

extern "C" void kernel_launch(void* const* d_in, const int* in_sizes, int n_in,
                              void* d_out, int out_size) {
    const float* quat    = (const float*)d_in[0];
    const float* tran    = (const float*)d_in[1];
    const float* model   = (const float*)d_in[2];
    const float* view    = (const float*)d_in[3];
    const float* centers = (const float*)d_in[4];
    const float* freev   = (const float*)d_in[5];
    const float* occo    = (const float*)d_in[6];
    const float* masks   = (const float*)d_in[7];
    (void)in_sizes; (void)n_in; (void)out_size;

    static bool attr_set = false;
    if (!attr_set) {
        cudaFuncSetAttribute(icc_kernel, cudaFuncAttributeMaxDynamicSharedMemorySize,
                             (int)sizeof(Smem));
        attr_set = true;
    }
    icc_kernel<<<GRID, TPB, sizeof(Smem)>>>(quat, tran, model, view, centers,
                                            freev, occo, masks, (float*)d_out);
}

// round 16
// speedup vs baseline: 1.0304x; 1.0304x over previous
#include <cuda_runtime.h>
#include <math.h>

#define M_PTS    2048
#define N_VOX    65536
#define TPB      512
#define GRID     (N_VOX / TPB)           // 128 blocks -> one wave on 148 SMs
#define PPT      (M_PTS / TPB)           // 4 points per thread
#define NPGRID   10                      // point grid: 10^3 cells, pitch 0.5 (q-space), [-2.5,2.5)
#define NPCELL   1000
#define NPPAD    1024
#define NWARPS   (TPB / 32)

__device__ float4 g_part[GRID];          // per-block partials {pred_sum, s1, s2, mask_sum}
__device__ unsigned g_done = 0;          // zero-init; self-resetting each run

__global__ void __launch_bounds__(TPB) icc_kernel(
    const float* __restrict__ quat,    const float* __restrict__ tran,
    const float* __restrict__ model,   const float* __restrict__ view,
    const float* __restrict__ centers, const float* __restrict__ freev,
    const float* __restrict__ occo,    const float* __restrict__ masks,
    float* __restrict__ out) {
    // static shared memory (~45.4 KB, fits default 48 KB limit; no attribute call)
    __shared__ float4 s_pts[M_PTS];           // block-private cell-sorted points (32 KB)
    __shared__ int    s_cnt[NPPAD];           // point histogram
    __shared__ int    s_cur[NPCELL];          // point scatter cursors
    __shared__ int    s_cstart[NPCELL + 1];
    __shared__ float  s_cof[16], s_iA[16], s_Em[16], s_Ms[16];
    __shared__ float  s_red[4][NWARPS];
    __shared__ int    s_wa[NWARPS];
    __shared__ unsigned s_amLast;

    const int t = threadIdx.x;
    const int lane = t & 31, w = t >> 5;

    // ---- voxel-side loads early (independent of everything) ----
    const int v = blockIdx.x * TPB + t;
    const float cx = centers[3 * v + 0];
    const float cy = centers[3 * v + 1];
    const float cz = centers[3 * v + 2];
    const float fo = freev[v] + occo[v];
    const float mk = masks[v];

    for (int i = t; i < NPPAD; i += TPB) s_cnt[i] = 0;

    // ---- parallel mat_world = inv(view) @ quat_matrix: 16 lanes, adjugate ----
    if (t < 16) {
        const int r = t >> 2, c = t & 3;
        float V[16];
#pragma unroll
        for (int k = 0; k < 16; k++) V[k] = view[k];
        int rr[3], cc[3];
        {
            int i0 = 0, i1 = 0;
#pragma unroll
            for (int k = 0; k < 4; k++) { if (k != r) rr[i0++] = k; if (k != c) cc[i1++] = k; }
        }
        float a00 = V[rr[0] * 4 + cc[0]], a01 = V[rr[0] * 4 + cc[1]], a02 = V[rr[0] * 4 + cc[2]];
        float a10 = V[rr[1] * 4 + cc[0]], a11 = V[rr[1] * 4 + cc[1]], a12 = V[rr[1] * 4 + cc[2]];
        float a20 = V[rr[2] * 4 + cc[0]], a21 = V[rr[2] * 4 + cc[1]], a22 = V[rr[2] * 4 + cc[2]];
        float det3 = a00 * (a11 * a22 - a12 * a21)
                   - a01 * (a10 * a22 - a12 * a20)
                   + a02 * (a10 * a21 - a11 * a20);
        s_cof[t] = (((r + c) & 1) ? -det3 : det3);     // cof[r*4+c]
        __syncwarp(0x0000ffffu);
        float det = V[0] * s_cof[0] + V[1] * s_cof[1] + V[2] * s_cof[2] + V[3] * s_cof[3];
        float rdet = 1.0f / det;
        s_iA[t] = s_cof[c * 4 + r] * rdet;             // inv[r][c] = cof[c][r]/det

        float q0 = quat[0], q1 = quat[1], q2 = quat[2], q3 = quat[3];
        float s = q0 * q0 + q1 * q1 + q2 * q2 + q3 * q3;
        float f = sqrtf(2.0f / s);
        q0 *= f; q1 *= f; q2 *= f; q3 *= f;
        float e;
        switch (t) {
            case 0:  e = 1.0f - q2 * q2 - q3 * q3; break;
            case 1:  e = q1 * q2 - q3 * q0;        break;
            case 2:  e = q1 * q3 + q2 * q0;        break;
            case 3:  e = tran[0];                  break;
            case 4:  e = q1 * q2 + q3 * q0;        break;
            case 5:  e = 1.0f - q1 * q1 - q3 * q3; break;
            case 6:  e = q2 * q3 - q1 * q0;        break;
            case 7:  e = tran[1];                  break;
            case 8:  e = q1 * q3 - q2 * q0;        break;
            case 9:  e = q2 * q3 + q1 * q0;        break;
            case 10: e = 1.0f - q1 * q1 - q2 * q2; break;
            case 11: e = tran[2];                  break;
            case 15: e = 1.0f;                     break;
            default: e = 0.0f;                     break;
        }
        s_Em[t] = e;
        __syncwarp(0x0000ffffu);
        s_Ms[t] = s_iA[r * 4 + 0] * s_Em[0 * 4 + c]
                + s_iA[r * 4 + 1] * s_Em[1 * 4 + c]
                + s_iA[r * 4 + 2] * s_Em[2 * 4 + c]
                + s_iA[r * 4 + 3] * s_Em[3 * 4 + c];
    }
    __syncthreads();

    // ---- transform 4 points/thread into registers; histogram ----
    float rx[PPT], ry[PPT], rz[PPT];
    int   rc[PPT];
#pragma unroll
    for (int k = 0; k < PPT; k++) {
        int i = k * TPB + t;                       // coalesced
        float mx = model[3 * i + 0], my = model[3 * i + 1], mz = model[3 * i + 2];
        float hx = s_Ms[0]  * mx + s_Ms[1]  * my + s_Ms[2]  * mz + s_Ms[3];
        float hy = s_Ms[4]  * mx + s_Ms[5]  * my + s_Ms[6]  * mz + s_Ms[7];
        float hz = s_Ms[8]  * mx + s_Ms[9]  * my + s_Ms[10] * mz + s_Ms[11];
        float hw = s_Ms[12] * mx + s_Ms[13] * my + s_Ms[14] * mz + s_Ms[15];
        float inv = 2.0f / hw;                      // pred / RES
        float x = hx * inv, y = hy * inv, z = hz * inv;
        rx[k] = x; ry[k] = y; rz[k] = z;
        int ix = (int)floorf(2.0f * x + 5.0f);
        int iy = (int)floorf(2.0f * y + 5.0f);
        int iz = (int)floorf(2.0f * z + 5.0f);
        int cell = -1;
        // points outside [-2.5,2.5)^3 are > 0.25 (L2) from every center in
        // [-2,2)^3 (q-space) -> the RES/2 clamp makes them irrelevant: discard.
        if (ix >= 0 && ix < NPGRID && iy >= 0 && iy < NPGRID && iz >= 0 && iz < NPGRID) {
            cell = (ix * NPGRID + iy) * NPGRID + iz;
            atomicAdd(&s_cnt[cell], 1);
        }
        rc[k] = cell;
    }
    __syncthreads();

    // ---- exclusive scan over 1024 point cells (2/thread) ----
    {
        int bidx = t * 2;
        int c0 = s_cnt[bidx], c1 = s_cnt[bidx + 1];
        int tot = c0 + c1;
        int incl = tot;
#pragma unroll
        for (int off = 1; off < 32; off <<= 1) {
            int u = __shfl_up_sync(0xffffffffu, incl, off);
            if (lane >= off) incl += u;
        }
        if (lane == 31) s_wa[w] = incl;
        __syncthreads();
        if (t < NWARPS) {
            int u = s_wa[t];
#pragma unroll
            for (int off = 1; off < NWARPS; off <<= 1) {
                int x2 = __shfl_up_sync(0x0000ffffu, u, off);
                if (t >= off) u += x2;
            }
            s_wa[t] = u;
        }
        __syncthreads();
        int excl = ((w > 0) ? s_wa[w - 1] : 0) + incl - tot;
        if (bidx < NPCELL)     { s_cstart[bidx]     = excl;      s_cur[bidx]     = excl; }
        if (bidx + 1 < NPCELL) { s_cstart[bidx + 1] = excl + c0; s_cur[bidx + 1] = excl + c0; }
        if (bidx == NPCELL) s_cstart[NPCELL] = excl;               // t=500: running total
    }
    __syncthreads();

    // ---- scatter points into block-private sorted table ----
#pragma unroll
    for (int k = 0; k < PPT; k++) {
        int cell = rc[k];
        if (cell >= 0) {
            int pos = atomicAdd(&s_cur[cell], 1);
            s_pts[pos] = make_float4(rx[k], ry[k], rz[k], 0.0f);
        }
    }
    __syncthreads();

    // ---- query: this thread's voxel against its 2x2x2 cell neighborhood ----
    const float ux = 2.0f * cx, uy = 2.0f * cy, uz = 2.0f * cz;
    const int ix0 = (int)floorf(4.0f * cx + 4.5f);   // in [0,8]
    const int iy0 = (int)floorf(4.0f * cy + 4.5f);
    const int iz0 = (int)floorf(4.0f * cz + 4.5f);

    float m0 = 1e30f, m1 = 1e30f, m2 = 1e30f, m3 = 1e30f;
#pragma unroll
    for (int a = 0; a < 2; a++) {
#pragma unroll
        for (int b = 0; b < 2; b++) {
            int cb = ((ix0 + a) * NPGRID + (iy0 + b)) * NPGRID + iz0;
            int s = s_cstart[cb];
            int e = s_cstart[cb + 2];                // z-cells iz0, iz0+1 contiguous
            int k = s;
            for (; k + 4 <= e; k += 4) {             // 4 independent chains
                float4 p0 = s_pts[k];
                float4 p1 = s_pts[k + 1];
                float4 p2 = s_pts[k + 2];
                float4 p3 = s_pts[k + 3];
                float dx0 = ux - p0.x, dy0 = uy - p0.y, dz0 = uz - p0.z;
                float dx1 = ux - p1.x, dy1 = uy - p1.y, dz1 = uz - p1.z;
                float dx2 = ux - p2.x, dy2 = uy - p2.y, dz2 = uz - p2.z;
                float dx3 = ux - p3.x, dy3 = uy - p3.y, dz3 = uz - p3.z;
                m0 = fminf(m0, fmaf(dx0, dx0, fmaf(dy0, dy0, dz0 * dz0)));
                m1 = fminf(m1, fmaf(dx1, dx1, fmaf(dy1, dy1, dz1 * dz1)));
                m2 = fminf(m2, fmaf(dx2, dx2, fmaf(dy2, dy2, dz2 * dz2)));
                m3 = fminf(m3, fmaf(dx3, dx3, fmaf(dy3, dy3, dz3 * dz3)));
            }
            for (; k < e; k++) {
                float4 p = s_pts[k];
                float dx = ux - p.x, dy = uy - p.y, dz = uz - p.z;
                m0 = fminf(m0, fmaf(dx, dx, fmaf(dy, dy, dz * dz)));
            }
        }
    }
    float m = fminf(fminf(m0, m1), fminf(m2, m3));

    float d = sqrtf(fmaxf(m, 0.0f));
    d = fminf(d, 0.25f);
    float o = fmaxf(1.0f - 4.0f * d, 0.0f);

    float aps = o, as1 = fo * o, as2 = mk * o, ams = mk;

    const unsigned full = 0xffffffffu;
#pragma unroll
    for (int off = 16; off > 0; off >>= 1) {
        aps += __shfl_down_sync(full, aps, off);
        as1 += __shfl_down_sync(full, as1, off);
        as2 += __shfl_down_sync(full, as2, off);
        ams += __shfl_down_sync(full, ams, off);
    }
    if (lane == 0) { s_red[0][w] = aps; s_red[1][w] = as1; s_red[2][w] = as2; s_red[3][w] = ams; }
    __syncthreads();
    if (t == 0) {
        float tps = 0.f, ts1 = 0.f, ts2 = 0.f, tms = 0.f;
#pragma unroll
        for (int i = 0; i < NWARPS; i++) {
            tps += s_red[0][i]; ts1 += s_red[1][i];
            ts2 += s_red[2][i]; tms += s_red[3][i];
        }
        g_part[blockIdx.x] = make_float4(tps, ts1, ts2, tms);
        __threadfence();
        unsigned r = atomicAdd(&g_done, 1u);
        s_amLast = (r == GRID - 1) ? 1u : 0u;
    }
    __syncthreads();

    // ---- last-finished block folds all partials into the scalar output ----
    if (s_amLast) {
        float4 p = (t < GRID) ? __ldcg(&g_part[t]) : make_float4(0.f, 0.f, 0.f, 0.f);
#pragma unroll
        for (int off = 16; off > 0; off >>= 1) {
            p.x += __shfl_down_sync(full, p.x, off);
            p.y += __shfl_down_sync(full, p.y, off);
            p.z += __shfl_down_sync(full, p.z, off);
            p.w += __shfl_down_sync(full, p.w, off);
        }
        if (lane == 0) { s_red[0][w] = p.x; s_red[1][w] = p.y; s_red[2][w] = p.z; s_red[3][w] = p.w; }
        __syncthreads();
        if (t == 0) {
            double ps = 0.0, s1 = 0.0, s2 = 0.0, ms = 0.0;
#pragma unroll
            for (int i = 0; i < NWARPS; i++) {
                ps += (double)s_red[0][i]; s1 += (double)s_red[1][i];
                s2 += (double)s_red[2][i]; ms += (double)s_red[3][i];
            }
            double t1 = (ps > 0.0) ? s1 / ps : 0.0;
            double t2 = (ms > 0.0) ? s2 / ms : 0.0;
            out[0] = (float)(t1 - t2);
            g_done = 0;                               // reset for next graph replay
        }
    }
}

extern "C" void kernel_launch(void* const* d_in, const int* in_sizes, int n_in,
                              void* d_out, int out_size) {
    const float* quat    = (const float*)d_in[0];
    const float* tran    = (const float*)d_in[1];
    const float* model   = (const float*)d_in[2];
    const float* view    = (const float*)d_in[3];
    const float* centers = (const float*)d_in[4];
    const float* freev   = (const float*)d_in[5];
    const float* occo    = (const float*)d_in[6];
    const float* masks   = (const float*)d_in[7];
    (void)in_sizes; (void)n_in; (void)out_size;

    icc_kernel<<<GRID, TPB>>>(quat, tran, model, view, centers,
                              freev, occo, masks, (float*)d_out);
}